// round 9
// baseline (speedup 1.0000x reference)
#include <cuda_runtime.h>
#include <cstdint>

#define NNODE 50000
#define NEDGE 800000
#define ETOT  850000   // NEDGE + NNODE self loops
#define CCH   64
#define LL    3
#define SLOPE 0.2f
#define WPB   4        // warps per block in layer kernel
#define NPW   8        // nodes per warp (software pipeline across nodes)
#define RSTR  68       // smem row stride in floats (272B, 16B-aligned)

// ---- packed f32x2 helpers (FFMA2/FADD2/FMUL2 are PTX-only on sm_103a) ----
union F2 { float2 f; unsigned long long u; };
#define FMA2(d, a, b, c) \
    asm("fma.rn.f32x2 %0, %1, %2, %3;" : "=l"((d).u) : "l"((a).u), "l"((b).u), "l"((c).u))
#define ADD2(d, a, b) \
    asm("add.rn.f32x2 %0, %1, %2;" : "=l"((d).u) : "l"((a).u), "l"((b).u))
#define MUL2(d, a, b) \
    asm("mul.rn.f32x2 %0, %1, %2;" : "=l"((d).u) : "l"((a).u), "l"((b).u))
#define PACK2(d, lo, hi) \
    asm("mov.b64 %0, {%1, %2};" : "=l"((d).u) : "r"(__float_as_uint(lo)), "r"(__float_as_uint(hi)))

// ---------------- static scratch ----------------
__device__ int   g_rowptr[NNODE + 1];
__device__ int   g_count[NNODE];
__device__ int   g_rank[ETOT];
__device__ int   g_src[ETOT];
__device__ float g_h0[NNODE * CCH];
__device__ float g_h1[NNODE * CCH];

// ---------------- CSR build (unchanged from round 7) ----------------
__global__ void zero_kernel() {
    int i = blockIdx.x * blockDim.x + threadIdx.x;
    if (i < NNODE) g_count[i] = 0;
}

__global__ void hist_kernel(const int* __restrict__ ei) {
    int i = blockIdx.x * blockDim.x + threadIdx.x;
    if (i >= ETOT / 4) return;
    int base = 4 * i;
    int d0, d1, d2, d3;
    if (base < NEDGE) {
        int4 d = *(const int4*)(ei + NEDGE + base);
        d0 = d.x; d1 = d.y; d2 = d.z; d3 = d.w;
    } else {
        d0 = base - NEDGE; d1 = d0 + 1; d2 = d0 + 2; d3 = d0 + 3;
    }
    int4 r;
    r.x = atomicAdd(&g_count[d0], 1);
    r.y = atomicAdd(&g_count[d1], 1);
    r.z = atomicAdd(&g_count[d2], 1);
    r.w = atomicAdd(&g_count[d3], 1);
    *(int4*)(g_rank + base) = r;
}

__global__ void scan_kernel() {
    __shared__ int wsum[33];
    __shared__ int carry_s;
    int tid = threadIdx.x, lane = tid & 31, wid = tid >> 5;
    if (tid == 0) carry_s = 0;
    __syncthreads();
    for (int base = 0; base < NNODE; base += 1024) {
        int i = base + tid;
        int v = (i < NNODE) ? g_count[i] : 0;
        int incl = v;
#pragma unroll
        for (int off = 1; off < 32; off <<= 1) {
            int t = __shfl_up_sync(0xffffffffu, incl, off);
            if (lane >= off) incl += t;
        }
        if (lane == 31) wsum[wid] = incl;
        __syncthreads();
        if (wid == 0) {
            int w = wsum[lane];
            int wincl = w;
#pragma unroll
            for (int off = 1; off < 32; off <<= 1) {
                int t = __shfl_up_sync(0xffffffffu, wincl, off);
                if (lane >= off) wincl += t;
            }
            wsum[lane] = wincl - w;
            if (lane == 31) wsum[32] = wincl;
        }
        __syncthreads();
        if (i < NNODE) g_rowptr[i] = carry_s + wsum[wid] + incl - v;
        __syncthreads();
        if (tid == 0) carry_s += wsum[32];
        __syncthreads();
    }
    if (threadIdx.x == 0) g_rowptr[NNODE] = ETOT;
}

__global__ void scatter_kernel(const int* __restrict__ ei) {
    int i = blockIdx.x * blockDim.x + threadIdx.x;
    if (i >= ETOT / 4) return;
    int base = 4 * i;
    int s0, s1, s2, s3, d0, d1, d2, d3;
    if (base < NEDGE) {
        int4 s = *(const int4*)(ei + base);
        int4 d = *(const int4*)(ei + NEDGE + base);
        s0 = s.x; s1 = s.y; s2 = s.z; s3 = s.w;
        d0 = d.x; d1 = d.y; d2 = d.z; d3 = d.w;
    } else {
        s0 = d0 = base - NEDGE;
        s1 = d1 = s0 + 1; s2 = d2 = s0 + 2; s3 = d3 = s0 + 3;
    }
    int4 r = *(const int4*)(g_rank + base);
    g_src[g_rowptr[d0] + r.x] = s0;
    g_src[g_rowptr[d1] + r.y] = s1;
    g_src[g_rowptr[d2] + r.z] = s2;
    g_src[g_rowptr[d3] + r.w] = s3;
}

// ------- fused layer: round-7 smem compute + cross-node/chunk prefetch -------
__global__ void __launch_bounds__(WPB * 32, 5) layer_kernel(
    int layer, const float* __restrict__ x0,
    const float* __restrict__ att, const float* __restrict__ bias,
    float* __restrict__ out)
{
    __shared__ float att_s[2 * CCH];
    __shared__ float xd_s[WPB][CCH];
    __shared__ float rows_s[WPB][16 * RSTR];

    int tid = threadIdx.x, lane = tid & 31, wid = tid >> 5;
    att_s[tid] = att[layer * 2 * CCH + tid];
    __syncthreads();

    int warpId = blockIdx.x * WPB + wid;
    int node0 = warpId * NPW;
    if (node0 >= NNODE) return;
    int kEnd = min(NPW, NNODE - node0);

    const float* x = (layer == 0) ? x0 : ((layer == 1) ? g_h0 : g_h1);
    int half = lane >> 4;       // edge sub-index parity / channel half
    int sub  = lane & 15;

    // rowptr slice for this warp's nodes (coalesced; served by shfl)
    int rpv = 0;
    if (lane <= kEnd) rpv = g_rowptr[node0 + lane];
    float2 bv = *(const float2*)(bias + layer * CCH + 2 * lane);

    // ---- prologue: node0's sidx window, x[dst] row, chunk-0 rows ----
    int start = __shfl_sync(0xffffffffu, rpv, 0);
    int end   = __shfl_sync(0xffffffffu, rpv, 1);
    int sidx_cur = (start + lane < end) ? g_src[start + lane] : 0;
    float4 xd_cur = make_float4(0.f, 0.f, 0.f, 0.f);
    if (lane < 16) xd_cur = *(const float4*)(x + (size_t)node0 * CCH + lane * 4);
    float4 r[8];
    {
        int cnt = min(16, end - start);
#pragma unroll
        for (int j = 0; j < 8; j++) {
            int rr = 2 * j + half;
            int sk = __shfl_sync(0xffffffffu, sidx_cur, rr);
            if (rr < cnt) r[j] = *(const float4*)(x + (size_t)sk * CCH + sub * 4);
        }
    }

    const float4* a4 = (const float4*)&att_s[half * 32];
    const float4* b4 = (const float4*)&att_s[CCH + half * 32];
    const float4* d4 = (const float4*)&xd_s[wid][half * 32];
    F2 c02; c02.f = make_float2(SLOPE, SLOPE);

    for (int k = 0; k < kEnd; k++) {
        int deg = end - start;
        int nch = (deg + 15) >> 4;

        // prefetch NEXT node's sidx window + x[dst] row (hidden across node k)
        int nstart = 0, nend = 0, sidx_nxt = 0;
        float4 xdn = make_float4(0.f, 0.f, 0.f, 0.f);
        if (k + 1 < kEnd) {
            nstart = __shfl_sync(0xffffffffu, rpv, k + 1);
            nend   = __shfl_sync(0xffffffffu, rpv, k + 2);
            sidx_nxt = (nstart + lane < nend) ? g_src[nstart + lane] : 0;
            if (lane < 16)
                xdn = *(const float4*)(x + (size_t)(node0 + k + 1) * CCH + lane * 4);
        }

        float s0 = 0.f, s1 = 0.f;
        F2 acc0, acc1;
        acc0.f = make_float2(0.f, 0.f);
        acc1.f = make_float2(0.f, 0.f);
        int swin = 0;

        for (int c = 0; c < nch; c++) {
            int cnt = min(16, deg - 16 * c);

            __syncwarp();   // WAR: prior smem reads done before restage
            if (c == 0 && lane < 16)
                *(float4*)&xd_s[wid][lane * 4] = xd_cur;
#pragma unroll
            for (int j = 0; j < 8; j++) {
                int rr = 2 * j + half;
                if (rr < cnt) *(float4*)&rows_s[wid][rr * RSTR + sub * 4] = r[j];
            }

            // prefetch next work item's rows into r[] (LDGs overlap compute)
            if (c + 1 < nch) {
                if (16 * (c + 1) >= swin + 32) {   // rare: deg > 32
                    swin += 32;
                    sidx_cur = (start + swin + lane < end)
                             ? g_src[start + swin + lane] : 0;
                }
                int base = 16 * (c + 1) - swin;
                int ncnt = min(16, deg - 16 * (c + 1));
#pragma unroll
                for (int j = 0; j < 8; j++) {
                    int rr = 2 * j + half;
                    int sk = __shfl_sync(0xffffffffu, sidx_cur, base + rr);
                    if (rr < ncnt)
                        r[j] = *(const float4*)(x + (size_t)sk * CCH + sub * 4);
                }
            } else if (k + 1 < kEnd) {
                int ncnt = min(16, nend - nstart);
#pragma unroll
                for (int j = 0; j < 8; j++) {
                    int rr = 2 * j + half;
                    int sk = __shfl_sync(0xffffffffu, sidx_nxt, rr);
                    if (rr < ncnt)
                        r[j] = *(const float4*)(x + (size_t)sk * CCH + sub * 4);
                }
            }
            __syncwarp();

            // logits: 2 lanes per edge, 32 channels each, f32x2 packed
            float p0 = -1e30f, p1 = -1e30f;
            if (sub < cnt) {
                F2 q0, q1;
                q0.f = make_float2(0.f, 0.f);
                q1.f = make_float2(0.f, 0.f);
                const float4* rp = (const float4*)&rows_s[wid][sub * RSTR + half * 32];
#pragma unroll
                for (int j = 0; j < 8; j++) {
                    float4 v = rp[j];
                    float4 d = d4[j];
                    F2 vlo, vhi, dlo, dhi;
                    vlo.f = make_float2(v.x, v.y); vhi.f = make_float2(v.z, v.w);
                    dlo.f = make_float2(d.x, d.y); dhi.f = make_float2(d.z, d.w);
                    F2 zlo, zhi, mlo, mhi, tlo, thi;
                    ADD2(zlo, vlo, dlo);
                    ADD2(zhi, vhi, dhi);
                    MUL2(mlo, zlo, c02);
                    MUL2(mhi, zhi, c02);
                    tlo.f.x = fmaxf(zlo.f.x, mlo.f.x);
                    tlo.f.y = fmaxf(zlo.f.y, mlo.f.y);
                    thi.f.x = fmaxf(zhi.f.x, mhi.f.x);
                    thi.f.y = fmaxf(zhi.f.y, mhi.f.y);
                    float4 a = a4[j], b = b4[j];
                    F2 alo, ahi, blo, bhi;
                    alo.f = make_float2(a.x, a.y); ahi.f = make_float2(a.z, a.w);
                    blo.f = make_float2(b.x, b.y); bhi.f = make_float2(b.z, b.w);
                    FMA2(q0, tlo, alo, q0);
                    FMA2(q0, thi, ahi, q0);
                    FMA2(q1, tlo, blo, q1);
                    FMA2(q1, thi, bhi, q1);
                }
                p0 = q0.f.x + q0.f.y;
                p1 = q1.f.x + q1.f.y;
            }
            p0 += __shfl_xor_sync(0xffffffffu, p0, 16);
            p1 += __shfl_xor_sync(0xffffffffu, p1, 16);

            // logits bounded: exp without max subtraction is exact-ratio
            float w0 = __expf(p0), w1 = __expf(p1);
            s0 += w0;
            s1 += w1;

            // aggregate from smem; weights via SHFL broadcast (dup in halves)
#pragma unroll 4
            for (int kk = 0; kk < cnt; kk++) {
                float wk0 = __shfl_sync(0xffffffffu, w0, kk);
                float wk1 = __shfl_sync(0xffffffffu, w1, kk);
                F2 wp0, wp1;
                PACK2(wp0, wk0, wk0);
                PACK2(wp1, wk1, wk1);
                F2 v; v.f = *(const float2*)&rows_s[wid][kk * RSTR + 2 * lane];
                FMA2(acc0, wp0, v, acc0);
                FMA2(acc1, wp1, v, acc1);
            }
        }

        // ---- finalize node node0+k ----
#pragma unroll
        for (int off = 16; off; off >>= 1) {
            s0 += __shfl_xor_sync(0xffffffffu, s0, off);
            s1 += __shfl_xor_sync(0xffffffffu, s1, off);
        }
        float inv0 = 1.0f / (s0 + 2e-16f);     // = 0.5/S (head-mean folded)
        float inv1 = 1.0f / (s1 + 2e-16f);
        float o0 = acc0.f.x * inv0 + acc1.f.x * inv1 + bv.x;
        float o1 = acc0.f.y * inv0 + acc1.f.y * inv1 + bv.y;

        int node = node0 + k;
        size_t ofs = (size_t)node * CCH + 2 * lane;
        if (layer < 2) {
            float* h = (layer == 0) ? g_h0 : g_h1;
            *(float2*)(h + ofs) = make_float2(o0, o1);
        }
        float2* op = (float2*)(out + ofs);
        if (layer == 0) {
            float2 xv = *(const float2*)&xd_s[wid][2 * lane];
            *op = make_float2(xv.x + o0, xv.y + o1);   // out poisoned: no read
        } else if (layer == 1) {
            float2 ov = *op;
            ov.x += o0; ov.y += o1;
            *op = ov;
        } else {
            float2 ov = *op;
            ov.x = (ov.x + o0) * 0.25f;
            ov.y = (ov.y + o1) * 0.25f;
            *op = ov;
        }

        // rotate pipeline state to next node
        start = nstart; end = nend;
        sidx_cur = sidx_nxt;
        xd_cur = xdn;
    }
}

// ---------------- launch ----------------
extern "C" void kernel_launch(void* const* d_in, const int* in_sizes, int n_in,
                              void* d_out, int out_size) {
    const float* x    = (const float*)d_in[0];
    const int*   ei   = (const int*)d_in[1];
    const float* att  = (const float*)d_in[2];
    const float* bias = (const float*)d_in[3];
    float* out = (float*)d_out;

    zero_kernel<<<(NNODE + 255) / 256, 256>>>();
    hist_kernel<<<(ETOT / 4 + 255) / 256, 256>>>(ei);
    scan_kernel<<<1, 1024>>>();
    scatter_kernel<<<(ETOT / 4 + 255) / 256, 256>>>(ei);

    int warps = (NNODE + NPW - 1) / NPW;
    dim3 grd((warps + WPB - 1) / WPB);
    for (int l = 0; l < LL; l++)
        layer_kernel<<<grd, WPB * 32>>>(l, x, att, bias, out);
}

// round 10
// speedup vs baseline: 1.3509x; 1.3509x over previous
#include <cuda_runtime.h>
#include <cstdint>

#define NNODE 50000
#define NEDGE 800000
#define ETOT  850000   // NEDGE + NNODE self loops
#define CCH   64
#define LL    3
#define SLOPE 0.2f
#define WPB   4        // warps per block in layer kernel
#define CH    16       // edges per subchunk
#define RSTR  68       // smem row stride in floats (16B aligned, conflict-free)

// ---- packed f32x2 helpers (FFMA2/FADD2/FMUL2 are PTX-only on sm_103a) ----
union F2 { float2 f; unsigned long long u; };
#define FMA2(d, a, b, c) \
    asm("fma.rn.f32x2 %0, %1, %2, %3;" : "=l"((d).u) : "l"((a).u), "l"((b).u), "l"((c).u))
#define ADD2(d, a, b) \
    asm("add.rn.f32x2 %0, %1, %2;" : "=l"((d).u) : "l"((a).u), "l"((b).u))
#define MUL2(d, a, b) \
    asm("mul.rn.f32x2 %0, %1, %2;" : "=l"((d).u) : "l"((a).u), "l"((b).u))
#define PACK2(d, lo, hi) \
    asm("mov.b64 %0, {%1, %2};" : "=l"((d).u) : "r"(__float_as_uint(lo)), "r"(__float_as_uint(hi)))

// ---------------- static scratch ----------------
__device__ int   g_rowptr[NNODE + 1];
__device__ int   g_count[NNODE];       // zero at load; re-zeroed by scan each call
__device__ int   g_rank[ETOT];         // per-edge arrival rank within its dst
__device__ int   g_src[ETOT];          // src*CCH per CSR slot (grouped by dst)
__device__ float g_h0[NNODE * CCH];
__device__ float g_h1[NNODE * CCH];

// ---------------- CSR build ----------------
// hist + rank record: 4 edges/thread, 4 atomics in flight; rank stored int4.
__global__ void hist_kernel(const int* __restrict__ ei) {
    int i = blockIdx.x * blockDim.x + threadIdx.x;
    if (i >= ETOT / 4) return;
    int base = 4 * i;
    int d0, d1, d2, d3;
    if (base < NEDGE) {
        int4 d = *(const int4*)(ei + NEDGE + base);
        d0 = d.x; d1 = d.y; d2 = d.z; d3 = d.w;
    } else {
        d0 = base - NEDGE; d1 = d0 + 1; d2 = d0 + 2; d3 = d0 + 3;
    }
    int4 r;
    r.x = atomicAdd(&g_count[d0], 1);
    r.y = atomicAdd(&g_count[d1], 1);
    r.z = atomicAdd(&g_count[d2], 1);
    r.w = atomicAdd(&g_count[d3], 1);
    *(int4*)(g_rank + base) = r;
}

// single-block warp-shuffle scan (exclusive) -> g_rowptr.
// Also re-zeroes g_count for the next kernel_launch call (graph replays the
// whole sequence, so every call observes zeroed counts — deterministic).
__global__ void scan_kernel() {
    __shared__ int wsum[33];
    __shared__ int carry_s;
    int tid = threadIdx.x, lane = tid & 31, wid = tid >> 5;
    if (tid == 0) carry_s = 0;
    __syncthreads();
    for (int base = 0; base < NNODE; base += 1024) {
        int i = base + tid;
        int v = (i < NNODE) ? g_count[i] : 0;
        int incl = v;
#pragma unroll
        for (int off = 1; off < 32; off <<= 1) {
            int t = __shfl_up_sync(0xffffffffu, incl, off);
            if (lane >= off) incl += t;
        }
        if (lane == 31) wsum[wid] = incl;
        __syncthreads();
        if (wid == 0) {
            int w = wsum[lane];
            int wincl = w;
#pragma unroll
            for (int off = 1; off < 32; off <<= 1) {
                int t = __shfl_up_sync(0xffffffffu, wincl, off);
                if (lane >= off) wincl += t;
            }
            wsum[lane] = wincl - w;
            if (lane == 31) wsum[32] = wincl;
        }
        __syncthreads();
        if (i < NNODE) {
            g_rowptr[i] = carry_s + wsum[wid] + incl - v;
            g_count[i] = 0;                    // reset for next call
        }
        __syncthreads();
        if (tid == 0) carry_s += wsum[32];
        __syncthreads();
    }
    if (threadIdx.x == 0) g_rowptr[NNODE] = ETOT;
}

// atomic-free scatter: position = rowptr[dst] + rank; stores src*CCH
__global__ void scatter_kernel(const int* __restrict__ ei) {
    int i = blockIdx.x * blockDim.x + threadIdx.x;
    if (i >= ETOT / 4) return;
    int base = 4 * i;
    int s0, s1, s2, s3, d0, d1, d2, d3;
    if (base < NEDGE) {
        int4 s = *(const int4*)(ei + base);
        int4 d = *(const int4*)(ei + NEDGE + base);
        s0 = s.x; s1 = s.y; s2 = s.z; s3 = s.w;
        d0 = d.x; d1 = d.y; d2 = d.z; d3 = d.w;
    } else {
        s0 = d0 = base - NEDGE;
        s1 = d1 = s0 + 1; s2 = d2 = s0 + 2; s3 = d3 = s0 + 3;
    }
    int4 r = *(const int4*)(g_rank + base);
    g_src[g_rowptr[d0] + r.x] = s0 * CCH;
    g_src[g_rowptr[d1] + r.y] = s1 * CCH;
    g_src[g_rowptr[d2] + r.z] = s2 * CCH;
    g_src[g_rowptr[d3] + r.w] = s3 * CCH;
}

// ------------- fused layer: shfl-fed chunks, minimal serial chain ------------
__global__ void __launch_bounds__(WPB * 32) layer_kernel(
    int layer, const float* __restrict__ x0,
    const float* __restrict__ att, const float* __restrict__ bias,
    float* __restrict__ out)
{
    __shared__ float att_s[2 * CCH];
    __shared__ float xd_s[WPB][CCH];
    __shared__ float rows_s[WPB][CH * RSTR];

    int tid = threadIdx.x, lane = tid & 31, wid = tid >> 5;
    att_s[tid] = att[layer * 2 * CCH + tid];           // 128 threads, 128 vals
    __syncthreads();

    int node = blockIdx.x * WPB + wid;
    if (node >= NNODE) return;

    const float* x = (layer == 0) ? x0 : ((layer == 1) ? g_h0 : g_h1);
    int start = g_rowptr[node];
    int end   = g_rowptr[node + 1];

    // x[dst] row -> shared (once per node)
    float2 xdv = *(const float2*)(x + (size_t)node * CCH + 2 * lane);
    *(float2*)&xd_s[wid][2 * lane] = xdv;
    __syncwarp();

    int half = lane >> 4;       // channel half / row parity
    int sub  = lane & 15;

    const float4* d4 = (const float4*)&xd_s[wid][half * 32];
    const float4* a4 = (const float4*)&att_s[half * 32];
    const float4* b4 = (const float4*)&att_s[CCH + half * 32];

    F2 c02; c02.f = make_float2(SLOPE, SLOPE);

    float s0 = 0.f, s1 = 0.f;                  // per-lane partial exp-sums
    F2 acc0, acc1;                              // packed accumulators (2 ch)
    acc0.f = make_float2(0.f, 0.f);
    acc1.f = make_float2(0.f, 0.f);

    for (int cs = start; cs < end; cs += 32) {
        // one coalesced load covers two 16-edge subchunks (pre-scaled offsets)
        int sidx32 = (cs + lane < end) ? g_src[cs + lane] : 0;
        int rem = end - cs;

#pragma unroll
        for (int sc = 0; sc < 2; sc++) {
            int off = sc * CH;
            if (off >= rem) break;
            int cnt = min(CH, rem - off);

            __syncwarp();  // WAR vs previous subchunk's smem reads
            // stage rows: fully unrolled, 8 predicated LDG.128s batched
#pragma unroll
            for (int rr = 0; rr < CH; rr += 2) {
                int r = rr + half;
                int sk = __shfl_sync(0xffffffffu, sidx32, off + r);
                if (r < cnt) {
                    float4 v = *(const float4*)(x + sk + sub * 4);
                    *(float4*)&rows_s[wid][r * RSTR + sub * 4] = v;
                }
            }
            __syncwarp();

            // logits: 2 lanes per edge, 32 channels each, f32x2 packed
            float p0 = -1e30f, p1 = -1e30f;
            if (sub < cnt) {
                F2 q0, q1;
                q0.f = make_float2(0.f, 0.f);
                q1.f = make_float2(0.f, 0.f);
                const float4* rp = (const float4*)&rows_s[wid][sub * RSTR + half * 32];
#pragma unroll
                for (int j = 0; j < 8; j++) {
                    float4 v = rp[j];
                    float4 d = d4[j];
                    F2 vlo, vhi, dlo, dhi;
                    vlo.f = make_float2(v.x, v.y); vhi.f = make_float2(v.z, v.w);
                    dlo.f = make_float2(d.x, d.y); dhi.f = make_float2(d.z, d.w);
                    F2 zlo, zhi, mlo, mhi, tlo, thi;
                    ADD2(zlo, vlo, dlo);
                    ADD2(zhi, vhi, dhi);
                    MUL2(mlo, zlo, c02);
                    MUL2(mhi, zhi, c02);
                    tlo.f.x = fmaxf(zlo.f.x, mlo.f.x);
                    tlo.f.y = fmaxf(zlo.f.y, mlo.f.y);
                    thi.f.x = fmaxf(zhi.f.x, mhi.f.x);
                    thi.f.y = fmaxf(zhi.f.y, mhi.f.y);
                    float4 a = a4[j], b = b4[j];
                    F2 alo, ahi, blo, bhi;
                    alo.f = make_float2(a.x, a.y); ahi.f = make_float2(a.z, a.w);
                    blo.f = make_float2(b.x, b.y); bhi.f = make_float2(b.z, b.w);
                    FMA2(q0, tlo, alo, q0);
                    FMA2(q0, thi, ahi, q0);
                    FMA2(q1, tlo, blo, q1);
                    FMA2(q1, thi, bhi, q1);
                }
                p0 = q0.f.x + q0.f.y;
                p1 = q1.f.x + q1.f.y;
            }
            // combine channel halves; invalid edges -> -2e30 -> exp = 0
            p0 += __shfl_xor_sync(0xffffffffu, p0, 16);
            p1 += __shfl_xor_sync(0xffffffffu, p1, 16);

            // logits bounded (|p| < ~10): exp without max subtraction is exact
            float w0 = __expf(p0), w1 = __expf(p1);
            s0 += w0;                      // both halves add -> 2x, folded below
            s1 += w1;

            // aggregate: weights via SHFL broadcast (w duplicated in both halves)
#pragma unroll 4
            for (int k = 0; k < cnt; k++) {
                float wk0 = __shfl_sync(0xffffffffu, w0, k);
                float wk1 = __shfl_sync(0xffffffffu, w1, k);
                F2 wp0, wp1;
                PACK2(wp0, wk0, wk0);
                PACK2(wp1, wk1, wk1);
                F2 v; v.f = *(const float2*)&rows_s[wid][k * RSTR + 2 * lane];
                FMA2(acc0, wp0, v, acc0);
                FMA2(acc1, wp1, v, acc1);
            }
        }
    }

    // one reduction at the end: sum over 32 lanes = 2 * S
#pragma unroll
    for (int off = 16; off; off >>= 1) {
        s0 += __shfl_xor_sync(0xffffffffu, s0, off);
        s1 += __shfl_xor_sync(0xffffffffu, s1, off);
    }
    float inv0 = 1.0f / (s0 + 2e-16f);          // = 0.5 / S (head-mean folded)
    float inv1 = 1.0f / (s1 + 2e-16f);

    float2 bv = *(const float2*)(bias + layer * CCH + 2 * lane);
    float o0 = acc0.f.x * inv0 + acc1.f.x * inv1 + bv.x;
    float o1 = acc0.f.y * inv0 + acc1.f.y * inv1 + bv.y;

    size_t o = (size_t)node * CCH + 2 * lane;
    if (layer < 2) {
        float* h = (layer == 0) ? g_h0 : g_h1;
        *(float2*)(h + o) = make_float2(o0, o1);
    }
    float2* op = (float2*)(out + o);
    if (layer == 0) {
        // out = feats[0] + h1 (out buffer is poisoned; do not read it)
        *op = make_float2(xdv.x + o0, xdv.y + o1);
    } else {
        float2 ov = *op;
        if (layer == 2) {  // fused final mean over {x, h1, h2, h3}
            ov.x = (ov.x + o0) * 0.25f;
            ov.y = (ov.y + o1) * 0.25f;
        } else {
            ov.x += o0; ov.y += o1;
        }
        *op = ov;
    }
}

// ---------------- launch ----------------
extern "C" void kernel_launch(void* const* d_in, const int* in_sizes, int n_in,
                              void* d_out, int out_size) {
    const float* x    = (const float*)d_in[0];
    const int*   ei   = (const int*)d_in[1];
    const float* att  = (const float*)d_in[2];
    const float* bias = (const float*)d_in[3];
    float* out = (float*)d_out;

    hist_kernel<<<(ETOT / 4 + 255) / 256, 256>>>(ei);
    scan_kernel<<<1, 1024>>>();
    scatter_kernel<<<(ETOT / 4 + 255) / 256, 256>>>(ei);

    dim3 grd((NNODE + WPB - 1) / WPB);
    for (int l = 0; l < LL; l++)
        layer_kernel<<<grd, WPB * 32>>>(l, x, att, bias, out);
}